// round 2
// baseline (speedup 1.0000x reference)
#include <cuda_runtime.h>

// MyLossJC: loss = -0.5/B * sum_{b,i,k} log(0.5*(alpha[b,i] + beta[b,i,k] + eps))
//   S[b,i,k]  = sum over pixels p with target[b,p]==k of z[b,i,p]
//   cnt[b,k]  = #pixels with target==k
//   alpha     = S[b,i,i]/cnt[b,i]              (0 if cnt==0)
//   beta      = (cnt[b,k]-S[b,i,k])/cnt[b,k]   (0 if cnt==0)

#define NB 8
#define NC 19
#define HWQ (512 * 512)           // 262144 pixels per batch
#define CH 2048                   // pixels per CTA tile
#define CHUNKS_PER_B (HWQ / CH)   // 128 (power of two)
#define NTHREADS (NC * 32)        // 608: one warp per channel

__device__ float g_S[NB * NC * NC];   // class-binned sums
__device__ float g_cnt[NB * NC];      // class pixel counts

__global__ void zero_kernel() {
    int i = blockIdx.x * blockDim.x + threadIdx.x;
    if (i < NB * NC * NC) g_S[i] = 0.0f;
    if (i < NB * NC)      g_cnt[i] = 0.0f;
}

__global__ __launch_bounds__(NTHREADS) void bin_kernel(
    const float* __restrict__ seg, const int* __restrict__ tgt)
{
    // bins[t][tid]: stride 608 is a multiple of 32 -> bank == lane id always,
    // so the dynamic-t accumulate is bank-conflict-free by construction.
    __shared__ float bins[NC * NTHREADS];           // 46208 B
    __shared__ unsigned tsm32[CH / 4];              // 2048 B (labels as bytes)
    __shared__ float csm[NC];

    int tid = threadIdx.x;
    int w = tid >> 5;        // warp id == channel id (0..18)
    int l = tid & 31;

    int b     = blockIdx.x >> 7;                 // CHUNKS_PER_B == 128
    int chunk = blockIdx.x & (CHUNKS_PER_B - 1);
    long p0   = (long)chunk * CH;

    if (tid < NC) csm[tid] = 0.0f;
    #pragma unroll
    for (int t = 0; t < NC; t++) bins[t * NTHREADS + tid] = 0.0f;
    __syncthreads();

    // Stage labels (int32 -> byte) into smem, histogram counts on the way.
    // Clamp defensively: an out-of-range label becomes a wrong answer
    // (caught by rel_err), never an OOB smem write.
    unsigned char* tsm = (unsigned char*)tsm32;
    const int* tb = tgt + (size_t)b * HWQ + p0;
    for (int j = tid; j < CH; j += NTHREADS) {
        int t = tb[j];
        t = (unsigned)t < NC ? t : 0;
        tsm[j] = (unsigned char)t;
        atomicAdd(&csm[t], 1.0f);
    }
    __syncthreads();

    if (tid < NC) atomicAdd(&g_cnt[b * NC + tid], csm[tid]);

    // Main loop: warp w sweeps channel w over the whole tile. float4 loads,
    // 4 labels per 32-bit smem read. Per-thread bin column -> no atomics.
    const float4* zb = (const float4*)(seg + ((size_t)b * NC + w) * HWQ + p0);
    float* binc = bins + tid;
    #pragma unroll 4
    for (int j = 0; j < CH / 128; j++) {
        float4 z4   = zb[j * 32 + l];
        unsigned tt = tsm32[j * 32 + l];
        binc[((tt      ) & 0xFF) * NTHREADS] += z4.x;
        binc[((tt >> 8 ) & 0xFF) * NTHREADS] += z4.y;
        binc[((tt >> 16) & 0xFF) * NTHREADS] += z4.z;
        binc[((tt >> 24)       ) * NTHREADS] += z4.w;
    }

    // Flush: warp-reduce each class bin across the warp's 32 private columns.
    float* Sout = g_S + ((size_t)b * NC + w) * NC;
    #pragma unroll 1
    for (int t = 0; t < NC; t++) {
        float v = bins[t * NTHREADS + tid];
        #pragma unroll
        for (int off = 16; off; off >>= 1)
            v += __shfl_xor_sync(0xFFFFFFFFu, v, off);
        if (l == 0) atomicAdd(&Sout[t], v);
    }
}

__global__ void finalize_kernel(float* __restrict__ out) {
    __shared__ float red[256];
    int tid = threadIdx.x;
    const float eps = 2.2204460492503131e-16f;
    float acc = 0.0f;
    for (int idx = tid; idx < NB * NC * NC; idx += 256) {
        int b = idx / (NC * NC);
        int r = idx - b * (NC * NC);
        int i = r / NC;
        int k = r - i * NC;
        float cnti = g_cnt[b * NC + i];
        float cntk = g_cnt[b * NC + k];
        float alpha = (cnti > 0.0f) ? g_S[(b * NC + i) * NC + i] / cnti : 0.0f;
        float beta  = (cntk > 0.0f) ? (cntk - g_S[(b * NC + i) * NC + k]) / cntk : 0.0f;
        acc += logf(0.5f * (alpha + beta + eps));
    }
    red[tid] = acc;
    __syncthreads();
    for (int off = 128; off; off >>= 1) {
        if (tid < off) red[tid] += red[tid + off];
        __syncthreads();
    }
    if (tid == 0) out[0] = -0.5f * red[0] / (float)NB;
}

extern "C" void kernel_launch(void* const* d_in, const int* in_sizes, int n_in,
                              void* d_out, int out_size)
{
    const float* seg = (const float*)d_in[0];
    const int*   tgt = (const int*)d_in[1];
    float*       out = (float*)d_out;

    zero_kernel<<<(NB * NC * NC + 255) / 256, 256>>>();
    bin_kernel<<<NB * CHUNKS_PER_B, NTHREADS>>>(seg, tgt);
    finalize_kernel<<<1, 256>>>(out);
}

// round 3
// speedup vs baseline: 1.2055x; 1.2055x over previous
#include <cuda_runtime.h>

// MyLossJC: loss = -0.5/B * sum_{b,i,k} log(0.5*(alpha[b,i] + beta[b,i,k] + eps))
//   S[b,i,k]  = sum over pixels p with target[b,p]==k of z[b,i,p]
//   cnt[b,k]  = #pixels with target==k
//   alpha     = S[b,i,i]/cnt[b,i]              (0 if cnt==0)
//   beta      = (cnt[b,k]-S[b,i,k])/cnt[b,k]   (0 if cnt==0)

#define NB 8
#define NC 19
#define HWQ (512 * 512)           // 262144 pixels per batch
#define CH 2048                   // pixels per CTA tile
#define CHUNKS_PER_B (HWQ / CH)   // 128 (power of two)
#define NTHREADS (NC * 32)        // 608: one warp per channel
#define PREF 8                    // float4 groups prefetched per batch

__device__ float g_S[NB * NC * NC];   // class-binned sums
__device__ float g_cnt[NB * NC];      // class pixel counts

__global__ void zero_kernel() {
    int i = blockIdx.x * blockDim.x + threadIdx.x;
    if (i < NB * NC * NC) g_S[i] = 0.0f;
    if (i < NB * NC)      g_cnt[i] = 0.0f;
}

__global__ void dummy_kernel() {}   // launch-order pad so ncu -s5 -c1 hits bin_kernel

__global__ __launch_bounds__(NTHREADS, 2) void bin_kernel(
    const float* __restrict__ seg, const int* __restrict__ tgt)
{
    // bins[t][tid]: stride 608 is a multiple of 32 -> bank == lane id always,
    // so the dynamic-t accumulate is bank-conflict-free by construction.
    __shared__ float bins[NC * NTHREADS];           // 46208 B
    __shared__ unsigned tsm32[CH / 4];              // 2048 B (labels as bytes)
    __shared__ float csm[NC];

    int tid = threadIdx.x;
    int w = tid >> 5;        // warp id == channel id (0..18)
    int l = tid & 31;

    int b     = blockIdx.x >> 7;                 // CHUNKS_PER_B == 128
    int chunk = blockIdx.x & (CHUNKS_PER_B - 1);
    long p0   = (long)chunk * CH;

    if (tid < NC) csm[tid] = 0.0f;
    #pragma unroll
    for (int t = 0; t < NC; t++) bins[t * NTHREADS + tid] = 0.0f;
    __syncthreads();

    // Stage labels (int32 -> byte) into smem, histogram counts on the way.
    unsigned char* tsm = (unsigned char*)tsm32;
    const int* tb = tgt + (size_t)b * HWQ + p0;
    for (int j = tid; j < CH; j += NTHREADS) {
        int t = tb[j];
        t = (unsigned)t < NC ? t : 0;
        tsm[j] = (unsigned char)t;
        atomicAdd(&csm[t], 1.0f);
    }
    __syncthreads();

    if (tid < NC) atomicAdd(&g_cnt[b * NC + tid], csm[tid]);

    // Main loop: warp w sweeps channel w over the tile.
    // Prefetch PREF independent float4 loads (MLP=PREF) before the smem RMWs
    // so DRAM latency is covered; the RMW chains then run against registers.
    const float4* zb = (const float4*)(seg + ((size_t)b * NC + w) * HWQ + p0);
    float* binc = bins + tid;
    #pragma unroll 1
    for (int g = 0; g < CH / (128 * PREF); g++) {   // 2 batches of 8 groups
        float4   z[PREF];
        unsigned tt[PREF];
        #pragma unroll
        for (int u = 0; u < PREF; u++) {
            z[u]  = zb[(g * PREF + u) * 32 + l];
            tt[u] = tsm32[(g * PREF + u) * 32 + l];
        }
        #pragma unroll
        for (int u = 0; u < PREF; u++) {
            binc[((tt[u]      ) & 0xFF) * NTHREADS] += z[u].x;
            binc[((tt[u] >> 8 ) & 0xFF) * NTHREADS] += z[u].y;
            binc[((tt[u] >> 16) & 0xFF) * NTHREADS] += z[u].z;
            binc[((tt[u] >> 24)       ) * NTHREADS] += z[u].w;
        }
    }
    __syncthreads();

    // Flush: 361 threads, each sums one (class t, channel w2) pair across the
    // 32 lane columns with a rotation stagger (bank == (l0+j)&31, conflict-free),
    // then a single global reduction-add.
    if (tid < NC * NC) {
        int t  = tid / NC;        // class k
        int w2 = tid - t * NC;    // channel i
        int l0 = tid & 31;
        const float* row = bins + t * NTHREADS + w2 * 32;
        float s = 0.0f;
        #pragma unroll
        for (int j = 0; j < 32; j++) s += row[(l0 + j) & 31];
        atomicAdd(&g_S[((size_t)b * NC + w2) * NC + t], s);
    }
}

__global__ void finalize_kernel(float* __restrict__ out) {
    __shared__ float red[256];
    int tid = threadIdx.x;
    const float eps = 2.2204460492503131e-16f;
    float acc = 0.0f;
    for (int idx = tid; idx < NB * NC * NC; idx += 256) {
        int b = idx / (NC * NC);
        int r = idx - b * (NC * NC);
        int i = r / NC;
        int k = r - i * NC;
        float cnti = g_cnt[b * NC + i];
        float cntk = g_cnt[b * NC + k];
        float alpha = (cnti > 0.0f) ? g_S[(b * NC + i) * NC + i] / cnti : 0.0f;
        float beta  = (cntk > 0.0f) ? (cntk - g_S[(b * NC + i) * NC + k]) / cntk : 0.0f;
        acc += logf(0.5f * (alpha + beta + eps));
    }
    red[tid] = acc;
    __syncthreads();
    for (int off = 128; off; off >>= 1) {
        if (tid < off) red[tid] += red[tid + off];
        __syncthreads();
    }
    if (tid == 0) out[0] = -0.5f * red[0] / (float)NB;
}

extern "C" void kernel_launch(void* const* d_in, const int* in_sizes, int n_in,
                              void* d_out, int out_size)
{
    const float* seg = (const float*)d_in[0];
    const int*   tgt = (const int*)d_in[1];
    float*       out = (float*)d_out;

    zero_kernel<<<(NB * NC * NC + 255) / 256, 256>>>();
    bin_kernel<<<NB * CHUNKS_PER_B, NTHREADS>>>(seg, tgt);
    finalize_kernel<<<1, 256>>>(out);
    dummy_kernel<<<1, 32>>>();   // pads launch order: #6 in profile = bin_kernel
}

// round 4
// speedup vs baseline: 1.2128x; 1.0060x over previous
#include <cuda_runtime.h>

// MyLossJC: loss = -0.5/B * sum_{b,i,k} log(0.5*(alpha[b,i] + beta[b,i,k] + eps))
//   S[b,i,k]  = sum over pixels p with target[b,p]==k of z[b,i,p]
//   cnt[b,k]  = #pixels with target==k
//   alpha     = S[b,i,i]/cnt[b,i]              (0 if cnt==0)
//   beta      = (cnt[b,k]-S[b,i,k])/cnt[b,k]   (0 if cnt==0)
//
// Self-restoring graph: g_S/g_cnt are zero-initialized at module load, and
// finalize_kernel re-zeros them after reading, so every replay starts clean
// with no separate zero_kernel launch.

#define NB 8
#define NC 19
#define HWQ (512 * 512)           // 262144 pixels per batch
#define CH 2048                   // pixels per CTA tile
#define CHUNKS_PER_B (HWQ / CH)   // 128 (power of two)
#define NTHREADS (NC * 32)        // 608: one warp per channel
#define PREF 8                    // float4 groups prefetched per batch

__device__ float g_S[NB * NC * NC];   // class-binned sums  (zero at load)
__device__ float g_cnt[NB * NC];      // class pixel counts (zero at load)

__global__ __launch_bounds__(NTHREADS, 1) void bin_kernel(
    const float* __restrict__ seg, const int* __restrict__ tgt)
{
    // bins[t][tid]: stride 608 is a multiple of 32 -> bank == lane id always,
    // so the dynamic-t accumulate is bank-conflict-free by construction.
    __shared__ float bins[NC * NTHREADS];           // 46208 B
    __shared__ unsigned tsm32[CH / 4];              // 2048 B (labels as bytes)
    __shared__ float csm[NC];

    int tid = threadIdx.x;
    int w = tid >> 5;        // warp id == channel id (0..18)
    int l = tid & 31;

    int b     = blockIdx.x >> 7;                 // CHUNKS_PER_B == 128
    int chunk = blockIdx.x & (CHUNKS_PER_B - 1);
    long p0   = (long)chunk * CH;

    if (tid < NC) csm[tid] = 0.0f;
    #pragma unroll
    for (int t = 0; t < NC; t++) bins[t * NTHREADS + tid] = 0.0f;
    __syncthreads();

    // Stage labels (int32 -> byte) into smem, histogram counts on the way.
    unsigned char* tsm = (unsigned char*)tsm32;
    const int* tb = tgt + (size_t)b * HWQ + p0;
    for (int j = tid; j < CH; j += NTHREADS) {
        int t = tb[j];
        t = (unsigned)t < NC ? t : 0;
        tsm[j] = (unsigned char)t;
        atomicAdd(&csm[t], 1.0f);
    }
    __syncthreads();

    if (tid < NC) atomicAdd(&g_cnt[b * NC + tid], csm[tid]);

    // Main loop: warp w sweeps channel w over the tile.
    // PREF independent LDG.128 are issued before any smem RMW (MLP=PREF);
    // occupancy cap 1 keeps the full prefetch batch in registers (no spill).
    const float4* zb = (const float4*)(seg + ((size_t)b * NC + w) * HWQ + p0);
    float* binc = bins + tid;
    #pragma unroll 1
    for (int g = 0; g < CH / (128 * PREF); g++) {   // 2 batches of 8 groups
        float4   z[PREF];
        unsigned tt[PREF];
        #pragma unroll
        for (int u = 0; u < PREF; u++) {
            z[u]  = zb[(g * PREF + u) * 32 + l];
            tt[u] = tsm32[(g * PREF + u) * 32 + l];
        }
        #pragma unroll
        for (int u = 0; u < PREF; u++) {
            binc[((tt[u]      ) & 0xFF) * NTHREADS] += z[u].x;
            binc[((tt[u] >> 8 ) & 0xFF) * NTHREADS] += z[u].y;
            binc[((tt[u] >> 16) & 0xFF) * NTHREADS] += z[u].z;
            binc[((tt[u] >> 24)       ) * NTHREADS] += z[u].w;
        }
    }
    __syncthreads();

    // Flush: 361 threads, each sums one (class t, channel w2) pair across the
    // 32 lane columns with a rotation stagger (bank-conflict-free), then one
    // global reduction-add.
    if (tid < NC * NC) {
        int t  = tid / NC;        // class k
        int w2 = tid - t * NC;    // channel i
        int l0 = tid & 31;
        const float* row = bins + t * NTHREADS + w2 * 32;
        float s = 0.0f;
        #pragma unroll
        for (int j = 0; j < 32; j++) s += row[(l0 + j) & 31];
        atomicAdd(&g_S[((size_t)b * NC + w2) * NC + t], s);
    }
}

__global__ void finalize_kernel(float* __restrict__ out) {
    __shared__ float red[256];
    int tid = threadIdx.x;
    const float eps = 2.2204460492503131e-16f;
    float acc = 0.0f;
    for (int idx = tid; idx < NB * NC * NC; idx += 256) {
        int b = idx / (NC * NC);
        int r = idx - b * (NC * NC);
        int i = r / NC;
        int k = r - i * NC;
        float cnti = g_cnt[b * NC + i];
        float cntk = g_cnt[b * NC + k];
        float alpha = (cnti > 0.0f) ? g_S[(b * NC + i) * NC + i] / cnti : 0.0f;
        float beta  = (cntk > 0.0f) ? (cntk - g_S[(b * NC + i) * NC + k]) / cntk : 0.0f;
        acc += logf(0.5f * (alpha + beta + eps));
    }
    red[tid] = acc;
    __syncthreads();

    // Restore globals to zero for the next graph replay.
    for (int idx = tid; idx < NB * NC * NC; idx += 256) g_S[idx] = 0.0f;
    if (tid < NB * NC) g_cnt[tid] = 0.0f;

    for (int off = 128; off; off >>= 1) {
        if (tid < off) red[tid] += red[tid + off];
        __syncthreads();
    }
    if (tid == 0) out[0] = -0.5f * red[0] / (float)NB;
}

extern "C" void kernel_launch(void* const* d_in, const int* in_sizes, int n_in,
                              void* d_out, int out_size)
{
    const float* seg = (const float*)d_in[0];
    const int*   tgt = (const int*)d_in[1];
    float*       out = (float*)d_out;

    bin_kernel<<<NB * CHUNKS_PER_B, NTHREADS>>>(seg, tgt);
    finalize_kernel<<<1, 256>>>(out);
}